// round 13
// baseline (speedup 1.0000x reference)
#include <cuda_runtime.h>
#include <cuda_fp16.h>
#include <cstdint>

#define TPB   256
#define PPB   512            // points per block (both personalities)
#define H     128

__device__ __forceinline__ unsigned h2u(__half2 v) { return *reinterpret_cast<unsigned*>(&v); }
__device__ __forceinline__ __half2 u2h(unsigned v) { return *reinterpret_cast<__half2*>(&v); }

__device__ __forceinline__ void mma8(unsigned& d0, unsigned& d1,
                                     unsigned a0, unsigned a1, unsigned b) {
    const unsigned z = 0;
    asm volatile("mma.sync.aligned.m16n8k8.row.col.f16.f16.f16.f16 "
                 "{%0,%1},{%2,%3},{%4},{%5,%6};"
                 : "=r"(d0), "=r"(d1)
                 : "r"(a0), "r"(a1), "r"(b), "r"(z), "r"(z));
}
__device__ __forceinline__ void mma16(float* c, unsigned a0, unsigned a1,
                                      unsigned a2, unsigned a3,
                                      unsigned b0, unsigned b1) {
    asm volatile("mma.sync.aligned.m16n8k16.row.col.f32.f16.f16.f32 "
                 "{%0,%1,%2,%3},{%4,%5,%6,%7},{%8,%9},{%0,%1,%2,%3};"
                 : "+f"(c[0]), "+f"(c[1]), "+f"(c[2]), "+f"(c[3])
                 : "r"(a0), "r"(a1), "r"(a2), "r"(a3), "r"(b0), "r"(b1));
}

// exact fp32 eval (z-rotation closed form)
__device__ __forceinline__ float eval_point(float x0, float x1, float x2,
                                            float theta, float sn, float cs) {
    const float d0 = x0 - theta, d1 = x1, d2 = x2;
    const float f1 = 1.4f * d0 * d0 + 1.4f * d1 * d1 + 0.2f * d2 * d2 - 0.5f;
    const float a2 = d2 + 0.4f;
    const float c20 = d0 * cs + d1 * sn, c21 = d1 * cs - d0 * sn;
    const float f2v = 3.8f * c20 * c20 + 0.6f * c21 * c21 + 3.8f * a2 * a2 - 0.5f;
    const float a3 = d2 - 0.6f;
    const float c30 = d0 * cs - d1 * sn, c31 = d0 * sn + d1 * cs;
    const float f3v = 0.35f * c30 * c30 + 2.8f * c31 * c31 + 2.8f * a3 * a3 - 0.5f;
    return fminf(f1, fminf(f2v, f3v));
}

__global__ __launch_bounds__(TPB, 4)   // 64-reg cap (tensor path fit at 64 in R12)
void cubeflow_hybrid_kernel(const float* __restrict__ input,
                            const float* __restrict__ latent,
                            const float* __restrict__ W1,
                            const float* __restrict__ b1,
                            const float* __restrict__ W2,
                            const float* __restrict__ b2,
                            float* __restrict__ out,
                            int P, int BP)
{
    // union-style smem: tensor path uses sCon; cuda path uses sW/sV/red
    __shared__ uint4  sCon[8 * 32];     // tensor: per-warp 32-pt staging
    __shared__ uint4  sW[H];            // cuda: {w0w0,w1w1,w2w2,bTbT}
    __shared__ uint4  sV[H / 2];        // cuda: {v0,v1} for 2 h
    __shared__ float4 redA[128];        // cuda: cross-half partials (pts 0,1)
    __shared__ float4 redB[128];        // cuda: cross-half partials (pts 2,3)

    const int bid  = blockIdx.x;
    const int rid  = bid >> 1;          // region-block index (0..511)
    const int tid  = threadIdx.x;

    if ((bid & 1) == 0) {
        // ================= TENSOR personality: points [0, BP/2) ===========
        const int lane = tid & 31;
        const int warp = tid >> 5;
        const int grp  = lane >> 2;
        const int tg   = lane & 3;
        const int wbase = rid * PPB + warp * 64;        // 64 pts per warp

        const float theta = latent[wbase / P] * 10.0f;
        float sn, cs;
        sincosf(theta, &sn, &cs);

        // B1 fragments: 16 hidden tiles, K cols [w0,w1,w2,0, bT,0,0,0]
        unsigned b1f[16];
        #pragma unroll
        for (int t = 0; t < 16; ++t) {
            const int h = 8 * t + grp;
            const float4 w = reinterpret_cast<const float4*>(W1)[h];
            const float bT = fmaf(w.w, theta, b1[h]);
            float lo, hi;
            if      (tg == 0) { lo = w.x; hi = w.y; }
            else if (tg == 1) { lo = w.z; hi = 0.f; }
            else if (tg == 2) { lo = bT;  hi = 0.f; }
            else              { lo = 0.f; hi = 0.f; }
            b1f[t] = h2u(__floats2half2_rn(lo, hi));
        }
        // B2 fragments: K=128 in 8 chunks; n=grp (pad n>=2 -> 0)
        unsigned b2f0[8], b2f1[8];
        #pragma unroll
        for (int u = 0; u < 8; ++u) {
            if (grp < 2) {
                const float* wr = W2 + grp * 128 + 16 * u + 2 * tg;
                b2f0[u] = h2u(__floats2half2_rn(wr[0], wr[1]));
                b2f1[u] = h2u(__floats2half2_rn(wr[8], wr[9]));
            } else { b2f0[u] = 0u; b2f1[u] = 0u; }
        }

        const float b20 = __ldg(b2), b21 = __ldg(b2 + 1);
        const __half2 hz = __float2half2_rn(0.0f);
        const uint32_t* swp = reinterpret_cast<const uint32_t*>(sCon);
        const int abase = (warp * 32 + grp) * 4 + tg;

        #pragma unroll 1
        for (int t = 0; t < 2; ++t) {
            const int tp0 = wbase + t * 32;
            const int p   = tp0 + lane;

            const float* ip = input + (size_t)p * 3;
            const float x0 = ip[0], x1 = ip[1], x2 = ip[2];
            sCon[warp * 32 + lane] =
                make_uint4(h2u(__floats2half2_rn(x0, x1)),
                           h2u(__floats2half2_rn(x2, 0.0f)),
                           h2u(__floats2half2_rn(1.0f, 0.0f)), 0u);

            reinterpret_cast<float4*>(out + BP)[p] = make_float4(x0, x1, x2, theta);
            out[p] = eval_point(x0, x1, x2, theta, sn, cs);

            __syncwarp();
            const unsigned a00 = swp[abase];
            const unsigned a01 = swp[abase + 32];
            const unsigned a10 = swp[abase + 64];
            const unsigned a11 = swp[abase + 96];
            __syncwarp();

            float acc0[4] = {0.f, 0.f, 0.f, 0.f};
            float acc1[4] = {0.f, 0.f, 0.f, 0.f};

            #pragma unroll
            for (int u = 0; u < 8; ++u) {
                unsigned d0, d1, e0, e1, f0, f1, g0, g1;
                mma8(d0, d1, a00, a01, b1f[2 * u]);
                mma8(e0, e1, a00, a01, b1f[2 * u + 1]);
                mma8(f0, f1, a10, a11, b1f[2 * u]);
                mma8(g0, g1, a10, a11, b1f[2 * u + 1]);
                d0 = h2u(__hmax2(u2h(d0), hz));  d1 = h2u(__hmax2(u2h(d1), hz));
                e0 = h2u(__hmax2(u2h(e0), hz));  e1 = h2u(__hmax2(u2h(e1), hz));
                f0 = h2u(__hmax2(u2h(f0), hz));  f1 = h2u(__hmax2(u2h(f1), hz));
                g0 = h2u(__hmax2(u2h(g0), hz));  g1 = h2u(__hmax2(u2h(g1), hz));
                mma16(acc0, d0, d1, e0, e1, b2f0[u], b2f1[u]);
                mma16(acc1, f0, f1, g0, g1, b2f0[u], b2f1[u]);
            }

            if (tg == 0) {
                float2* prp = reinterpret_cast<float2*>(out + (size_t)5 * BP);
                const int q0 = tp0 + grp;
                prp[q0]      = make_float2(acc0[0] + b20, acc0[1] + b21);
                prp[q0 + 8]  = make_float2(acc0[2] + b20, acc0[3] + b21);
                prp[q0 + 16] = make_float2(acc1[0] + b20, acc1[1] + b21);
                prp[q0 + 24] = make_float2(acc1[2] + b20, acc1[3] + b21);
            }
        }
    } else {
        // ================= CUDA-core personality: points [BP/2, BP) =======
        const int wg_tid = tid & 127;
        const int halfid = tid >> 7;            // 0: h[0,64)  1: h[64,128)
        const int base   = BP / 2 + rid * PPB;  // block's first point
        const float theta = latent[base / P] * 10.0f;

        // stage fp16 weights (theta-bias folded)
        if (tid < H) {
            const float4 r = reinterpret_cast<const float4*>(W1)[tid];
            const float bT = fmaf(r.w, theta, b1[tid]);
            sW[tid] = make_uint4(h2u(__float2half2_rn(r.x)),
                                 h2u(__float2half2_rn(r.y)),
                                 h2u(__float2half2_rn(r.z)),
                                 h2u(__float2half2_rn(bT)));
        } else if (tid < H + H / 2) {
            const int i = tid - H, h0 = 2 * i, h1 = h0 + 1;
            sV[i] = make_uint4(h2u(__float2half2_rn(W2[h0])),
                               h2u(__float2half2_rn(W2[H + h0])),
                               h2u(__float2half2_rn(W2[h1])),
                               h2u(__float2half2_rn(W2[H + h1])));
        }

        const int p0 = base + wg_tid * 4;       // this thread's 4 points
        const float4* in4 = reinterpret_cast<const float4*>(input + (size_t)p0 * 3);
        const float4 q0 = in4[0], q1 = in4[1], q2 = in4[2];
        const float x0[4] = { q0.x, q0.w, q1.z, q2.y };
        const float x1[4] = { q0.y, q1.x, q1.w, q2.z };
        const float x2[4] = { q0.z, q1.y, q2.x, q2.w };

        if (halfid == 0) {
            float4* conp = reinterpret_cast<float4*>(out + BP) + p0;
            #pragma unroll
            for (int k = 0; k < 4; ++k)
                conp[k] = make_float4(x0[k], x1[k], x2[k], theta);
        } else {
            float sn, cs;
            sincosf(theta, &sn, &cs);
            float ev[4];
            #pragma unroll
            for (int k = 0; k < 4; ++k)
                ev[k] = eval_point(x0[k], x1[k], x2[k], theta, sn, cs);
            *reinterpret_cast<float4*>(out + p0) =
                make_float4(ev[0], ev[1], ev[2], ev[3]);
        }

        // fp16 MLP, two adjacent points per half2 lane, this half's 64 h
        __half2 X0[2], X1[2], X2[2];
        float2  A0[2], A1[2];
        #pragma unroll
        for (int j = 0; j < 2; ++j) {
            X0[j] = __floats2half2_rn(x0[2 * j], x0[2 * j + 1]);
            X1[j] = __floats2half2_rn(x1[2 * j], x1[2 * j + 1]);
            X2[j] = __floats2half2_rn(x2[2 * j], x2[2 * j + 1]);
            A0[j] = make_float2(0.f, 0.f);
            A1[j] = make_float2(0.f, 0.f);
        }
        __syncthreads();

        const uint4* pw = sW + halfid * 64;
        const uint4* pv = sV + halfid * 32;
        const __half2 zero = __float2half2_rn(0.f);

        #pragma unroll 1
        for (int c = 0; c < 8; ++c) {           // 8 chunks of 8 h
            __half2 P0[2], P1[2];
            #pragma unroll
            for (int j = 0; j < 2; ++j) { P0[j] = zero; P1[j] = zero; }
            #pragma unroll
            for (int i = 0; i < 8; ++i) {
                const uint4 w = pw[c * 8 + i];
                const uint4 v = pv[c * 4 + (i >> 1)];
                const __half2 w0 = u2h(w.x), w1 = u2h(w.y);
                const __half2 w2 = u2h(w.z), bT = u2h(w.w);
                const __half2 v0 = u2h((i & 1) ? v.z : v.x);
                const __half2 v1 = u2h((i & 1) ? v.w : v.y);
                #pragma unroll
                for (int j = 0; j < 2; ++j) {
                    __half2 tt = __hfma2(w0, X0[j],
                                 __hfma2(w1, X1[j],
                                 __hfma2(w2, X2[j], bT)));
                    tt = __hmax2(tt, zero);
                    P0[j] = __hfma2(v0, tt, P0[j]);
                    P1[j] = __hfma2(v1, tt, P1[j]);
                }
            }
            #pragma unroll
            for (int j = 0; j < 2; ++j) {
                const float2 f0 = __half22float2(P0[j]);
                const float2 f1 = __half22float2(P1[j]);
                A0[j].x += f0.x;  A0[j].y += f0.y;
                A1[j].x += f1.x;  A1[j].y += f1.y;
            }
        }

        float pr0[4] = { A0[0].x, A0[0].y, A0[1].x, A0[1].y };
        float pr1[4] = { A1[0].x, A1[0].y, A1[1].x, A1[1].y };

        if (halfid == 1) {
            redA[wg_tid] = make_float4(pr0[0], pr1[0], pr0[1], pr1[1]);
            redB[wg_tid] = make_float4(pr0[2], pr1[2], pr0[3], pr1[3]);
        }
        __syncthreads();

        if (halfid == 0) {
            const float b20 = __ldg(b2), b21 = __ldg(b2 + 1);
            const float4 rA = redA[wg_tid];
            const float4 rB = redB[wg_tid];
            float4* prp = reinterpret_cast<float4*>(out + (size_t)5 * BP
                                                    + (size_t)p0 * 2);
            prp[0] = make_float4(pr0[0] + rA.x + b20, pr1[0] + rA.y + b21,
                                 pr0[1] + rA.z + b20, pr1[1] + rA.w + b21);
            prp[1] = make_float4(pr0[2] + rB.x + b20, pr1[2] + rB.y + b21,
                                 pr0[3] + rB.z + b20, pr1[3] + rB.w + b21);
        }
    }
}

extern "C" void kernel_launch(void* const* d_in, const int* in_sizes, int n_in,
                              void* d_out, int out_size)
{
    const float* input  = (const float*)d_in[0];
    const float* latent = (const float*)d_in[1];
    const float* W1     = (const float*)d_in[2];
    const float* b1     = (const float*)d_in[3];
    const float* W2     = (const float*)d_in[4];
    const float* b2     = (const float*)d_in[5];
    float*       out    = (float*)d_out;

    const int BP = in_sizes[0] / 3;     // total points (B*P)
    const int B  = in_sizes[1];
    const int P  = BP / B;
    const int blocks = BP / PPB;        // 1024 (512 tensor + 512 cuda, interleaved)

    cubeflow_hybrid_kernel<<<blocks, TPB>>>(input, latent, W1, b1, W2, b2,
                                            out, P, BP);
}